// round 1
// baseline (speedup 1.0000x reference)
#include <cuda_runtime.h>
#include <math.h>
#include <math_constants.h>

#define NLAYER 12
#define NHEAD  12
#define CDIM   768
#define HSZ    64
#define VOCAB  50304
#define BBATCH 2
#define TSEQ   1024
#define NTOK   (BBATCH * TSEQ)
#define C3     (3 * CDIM)
#define C4     (4 * CDIM)
#define MINKEEP 64

// ---------------- static device scratch (no allocation allowed) ----------------
__device__ float g_x[NTOK * CDIM];
__device__ float g_h[NTOK * CDIM];
__device__ float g_qkv[NTOK * C3];
__device__ float g_y[NTOK * CDIM];
__device__ float g_fc[NTOK * C4];
__device__ float g_att[(long)BBATCH * NHEAD * TSEQ * TSEQ];
__device__ float g_am[NTOK];
__device__ float g_imp[NTOK];
__device__ float g_nll[NTOK];

// ---------------- generic tiled SGEMM: C = A*B (+bias)(+resid)(gelu) ----------------
// A: M x K row-major (lda), B: K x N (ldb) or, if TRANSB, stored N x K (ldb = K-stride).
// Batched via blockIdx.z with element strides sA/sB/sC (resid uses ldc/sC layout).
template <bool TRANSB, int ACT>
__global__ __launch_bounds__(256) void gemm_kernel(
    const float* __restrict__ A, int lda, long sA,
    const float* __restrict__ Bp, int ldb, long sB,
    const float* __restrict__ bias,
    const float* resid,
    float* Cp, int ldc, long sC,
    int M, int N, int K)
{
    __shared__ float As[16][64];
    __shared__ float Bs[16][64];

    long z = blockIdx.z;
    A  += z * sA;
    Bp += z * sB;
    Cp += z * sC;
    if (resid) resid += z * sC;

    int bx = blockIdx.x * 64;
    int by = blockIdx.y * 64;
    int tid = threadIdx.x;
    int tx = tid & 15, ty = tid >> 4;

    float acc[4][4] = {};

    int arow = tid >> 2;          // 0..63
    int ak4  = (tid & 3) * 4;     // 0,4,8,12

    for (int k0 = 0; k0 < K; k0 += 16) {
        // load A tile (64 x 16), store transposed As[k][m]
        float4 av = *(const float4*)(A + (long)(by + arow) * lda + k0 + ak4);
        As[ak4 + 0][arow] = av.x;
        As[ak4 + 1][arow] = av.y;
        As[ak4 + 2][arow] = av.z;
        As[ak4 + 3][arow] = av.w;

        if (!TRANSB) {
            int bk = tid >> 4;            // 0..15
            int bn4 = (tid & 15) * 4;     // 0..60
            float4 bv = *(const float4*)(Bp + (long)(k0 + bk) * ldb + bx + bn4);
            *(float4*)&Bs[bk][bn4] = bv;
        } else {
            int bn  = tid >> 2;           // 0..63
            int bk4 = (tid & 3) * 4;      // 0,4,8,12
            float4 bv = *(const float4*)(Bp + (long)(bx + bn) * ldb + k0 + bk4);
            Bs[bk4 + 0][bn] = bv.x;
            Bs[bk4 + 1][bn] = bv.y;
            Bs[bk4 + 2][bn] = bv.z;
            Bs[bk4 + 3][bn] = bv.w;
        }
        __syncthreads();

        #pragma unroll
        for (int kk = 0; kk < 16; kk++) {
            float4 a4 = *(const float4*)&As[kk][ty * 4];
            float4 b4 = *(const float4*)&Bs[kk][tx * 4];
            float ar[4] = {a4.x, a4.y, a4.z, a4.w};
            float br[4] = {b4.x, b4.y, b4.z, b4.w};
            #pragma unroll
            for (int i = 0; i < 4; i++)
                #pragma unroll
                for (int j = 0; j < 4; j++)
                    acc[i][j] = fmaf(ar[i], br[j], acc[i][j]);
        }
        __syncthreads();
    }

    #pragma unroll
    for (int i = 0; i < 4; i++) {
        int m = by + ty * 4 + i;
        #pragma unroll
        for (int j = 0; j < 4; j++) {
            int n = bx + tx * 4 + j;
            float v = acc[i][j];
            if (bias)  v += bias[n];
            if (resid) v += resid[(long)m * ldc + n];
            if (ACT == 1) v = 0.5f * v * (1.0f + erff(v * 0.70710678118654752f));
            Cp[(long)m * ldc + n] = v;
        }
    }
}

// ---------------- layernorm: one block per row ----------------
__global__ void ln_kernel(const float* __restrict__ x, const float* __restrict__ w,
                          const float* __restrict__ b, float* __restrict__ out)
{
    int row = blockIdx.x;
    const float* xr = x + (long)row * CDIM;
    int tid = threadIdx.x;  // 256
    float v[3];
    float s = 0.f, s2 = 0.f;
    #pragma unroll
    for (int i = 0; i < 3; i++) {
        int c = tid + i * 256;
        float t = xr[c];
        v[i] = t;
        s += t;
        s2 += t * t;
    }
    __shared__ float r1[256], r2[256];
    r1[tid] = s; r2[tid] = s2;
    __syncthreads();
    for (int st = 128; st > 0; st >>= 1) {
        if (tid < st) { r1[tid] += r1[tid + st]; r2[tid] += r2[tid + st]; }
        __syncthreads();
    }
    float mean = r1[0] * (1.0f / CDIM);
    float var  = r2[0] * (1.0f / CDIM) - mean * mean;
    float rstd = rsqrtf(var + 1e-5f);
    float* orow = out + (long)row * CDIM;
    #pragma unroll
    for (int i = 0; i < 3; i++) {
        int c = tid + i * 256;
        orow[c] = (v[i] - mean) * rstd * w[c] + b[c];
    }
}

// ---------------- embedding ----------------
__global__ void embed_kernel(const int* __restrict__ idx, const float* __restrict__ wte,
                             const float* __restrict__ wpe, float* __restrict__ x)
{
    int row = blockIdx.x;
    int t = row % TSEQ;
    int tok = idx[row];
    const float* we = wte + (long)tok * CDIM;
    const float* wp = wpe + (long)t * CDIM;
    float* xr = x + (long)row * CDIM;
    for (int c = threadIdx.x; c < CDIM; c += 256)
        xr[c] = we[c] + wp[c];
}

__global__ void init_am_kernel(float* am)
{
    int i = blockIdx.x * 256 + threadIdx.x;
    if (i < NTOK) am[i] = 1.0f;
}

__global__ void zero_kernel(float* p, int n)
{
    int i = blockIdx.x * 256 + threadIdx.x;
    if (i < n) p[i] = 0.0f;
}

// ---------------- softmax + causal + key-mask, one block per (b,h,q) row ----------------
__global__ void softmax_mask_kernel(float* __restrict__ att, const float* __restrict__ am)
{
    long z = blockIdx.x;             // z = (b*H + h)*T + q
    int q = (int)(z % TSEQ);
    int b = (int)(z / ((long)NHEAD * TSEQ));
    float* row = att + z * TSEQ;
    const float* amr = am + (long)b * TSEQ;
    int tid = threadIdx.x;  // 256

    float vals[4];
    float lmax = -CUDART_INF_F;
    #pragma unroll
    for (int i = 0; i < 4; i++) {
        int k = tid + i * 256;
        float sc = row[k] * 0.125f;                   // 1/sqrt(64)
        bool valid = (k <= q) && (amr[k] > 0.0f);
        sc = valid ? sc : -CUDART_INF_F;
        vals[i] = sc;
        lmax = fmaxf(lmax, sc);
    }
    __shared__ float red[256];
    red[tid] = lmax;
    __syncthreads();
    for (int st = 128; st > 0; st >>= 1) {
        if (tid < st) red[tid] = fmaxf(red[tid], red[tid + st]);
        __syncthreads();
    }
    float m = red[0];
    __syncthreads();

    float lsum = 0.f;
    #pragma unroll
    for (int i = 0; i < 4; i++) {
        float e = expf(vals[i] - m);   // -inf - finite -> 0; all -inf -> NaN (matches jax)
        vals[i] = e;
        lsum += e;
    }
    red[tid] = lsum;
    __syncthreads();
    for (int st = 128; st > 0; st >>= 1) {
        if (tid < st) red[tid] += red[tid + st];
        __syncthreads();
    }
    float inv = 1.0f / red[0];
    #pragma unroll
    for (int i = 0; i < 4; i++) {
        int k = tid + i * 256;
        row[k] = vals[i] * inv;
    }
}

// ---------------- importance reduce: imp[b,k] += sum over h, q-chunk ----------------
__global__ void imp_reduce_kernel(const float* __restrict__ att, float* __restrict__ imp)
{
    int b = blockIdx.x;
    int k = blockIdx.y * 256 + threadIdx.x;
    int q0 = blockIdx.z * (TSEQ / 16);   // 64 queries per block
    float s = 0.f;
    for (int h = 0; h < NHEAD; h++) {
        const float* base = att + ((long)(b * NHEAD + h) * TSEQ) * TSEQ + k;
        #pragma unroll 4
        for (int q = q0; q < q0 + TSEQ / 16; q++)
            s += base[(long)q * TSEQ];
    }
    atomicAdd(&imp[b * TSEQ + k], s);
}

// ---------------- pruning mask update ----------------
__global__ void prune_mask_kernel(const float* __restrict__ imp, float* __restrict__ am,
                                  const float* __restrict__ thresholds, int layer)
{
    int i = blockIdx.x * 256 + threadIdx.x;
    if (i >= NTOK) return;
    int t = i % TSEQ;
    float th = thresholds[layer];
    float v = imp[i] * (1.0f / ((float)NHEAD * (float)TSEQ));
    float pm = (t >= TSEQ - MINKEEP) ? 1.0f : ((v >= th) ? 1.0f : 0.0f);  // NaN>=th -> false
    am[i] = am[i] * pm;
}

__global__ void scale_rows_kernel(float* __restrict__ x, const float* __restrict__ am)
{
    int row = blockIdx.x;
    float s = am[row];
    float* xr = x + (long)row * CDIM;
    for (int c = threadIdx.x; c < CDIM; c += 256)
        xr[c] *= s;
}

// ---------------- loss: per-row logsumexp + nll ----------------
__global__ void loss_row_kernel(const float* __restrict__ logits, const int* __restrict__ targets,
                                float* __restrict__ nll)
{
    int row = blockIdx.x;
    const float* lr = logits + (long)row * VOCAB;
    int tid = threadIdx.x;  // 256
    float m = -CUDART_INF_F;
    for (int c = tid; c < VOCAB; c += 256) m = fmaxf(m, lr[c]);
    __shared__ float red[256];
    red[tid] = m;
    __syncthreads();
    for (int st = 128; st > 0; st >>= 1) {
        if (tid < st) red[tid] = fmaxf(red[tid], red[tid + st]);
        __syncthreads();
    }
    m = red[0];
    __syncthreads();
    float s = 0.f;
    for (int c = tid; c < VOCAB; c += 256) s += expf(lr[c] - m);
    red[tid] = s;
    __syncthreads();
    for (int st = 128; st > 0; st >>= 1) {
        if (tid < st) red[tid] += red[tid + st];
        __syncthreads();
    }
    if (tid == 0) {
        int tgt = targets[row];
        float v = 0.f;
        if (tgt != -1) v = m + logf(red[0]) - lr[tgt];
        nll[row] = v;
    }
}

__global__ void loss_final_kernel(const float* __restrict__ nll, const int* __restrict__ targets,
                                  float* __restrict__ out)
{
    int tid = threadIdx.x;  // 256
    float s = 0.f;
    float cnt = 0.f;
    for (int i = tid; i < NTOK; i += 256) {
        if (targets[i] != -1) { s += nll[i]; cnt += 1.f; }
    }
    __shared__ float r1[256], r2[256];
    r1[tid] = s; r2[tid] = cnt;
    __syncthreads();
    for (int st = 128; st > 0; st >>= 1) {
        if (tid < st) { r1[tid] += r1[tid + st]; r2[tid] += r2[tid + st]; }
        __syncthreads();
    }
    if (tid == 0) out[0] = r1[0] / r2[0];
}

// ---------------- host orchestration ----------------
extern "C" void kernel_launch(void* const* d_in, const int* in_sizes, int n_in,
                              void* d_out, int out_size)
{
    const int*   idx        = (const int*)d_in[0];
    const int*   targets    = (const int*)d_in[1];
    const float* wte        = (const float*)d_in[2];
    const float* wpe        = (const float*)d_in[3];
    const float* ln1_w      = (const float*)d_in[4];
    const float* ln1_b      = (const float*)d_in[5];
    const float* attn_w     = (const float*)d_in[6];
    const float* attn_b     = (const float*)d_in[7];
    const float* proj_w     = (const float*)d_in[8];
    const float* proj_b     = (const float*)d_in[9];
    const float* ln2_w      = (const float*)d_in[10];
    const float* ln2_b      = (const float*)d_in[11];
    const float* fc_w       = (const float*)d_in[12];
    const float* fc_b       = (const float*)d_in[13];
    const float* mlp_w      = (const float*)d_in[14];
    const float* mlp_b      = (const float*)d_in[15];
    const float* thresholds = (const float*)d_in[16];
    const float* lnf_w      = (const float*)d_in[17];
    const float* lnf_b      = (const float*)d_in[18];

    float *x, *h, *qkv, *y, *fc, *att, *am, *imp, *nll;
    cudaGetSymbolAddress((void**)&x,   g_x);
    cudaGetSymbolAddress((void**)&h,   g_h);
    cudaGetSymbolAddress((void**)&qkv, g_qkv);
    cudaGetSymbolAddress((void**)&y,   g_y);
    cudaGetSymbolAddress((void**)&fc,  g_fc);
    cudaGetSymbolAddress((void**)&att, g_att);
    cudaGetSymbolAddress((void**)&am,  g_am);
    cudaGetSymbolAddress((void**)&imp, g_imp);
    cudaGetSymbolAddress((void**)&nll, g_nll);

    float* out = (float*)d_out;

    embed_kernel<<<NTOK, 256>>>(idx, wte, wpe, x);
    init_am_kernel<<<NTOK / 256, 256>>>(am);

    for (int l = 0; l < NLAYER; l++) {
        // LN1
        ln_kernel<<<NTOK, 256>>>(x, ln1_w + (long)l * CDIM, ln1_b + (long)l * CDIM, h);

        // qkv = h @ attn_w + attn_b  (2048 x 2304, K=768)
        gemm_kernel<false, 0><<<dim3(C3 / 64, NTOK / 64, 1), 256>>>(
            h, CDIM, 0,
            attn_w + (long)l * CDIM * C3, C3, 0,
            attn_b + (long)l * C3, nullptr,
            qkv, C3, 0, NTOK, C3, CDIM);

        // raw scores: S[bh] = Q Kᵀ  (batched over heads, per batch sample)
        for (int b = 0; b < BBATCH; b++) {
            gemm_kernel<true, 0><<<dim3(TSEQ / 64, TSEQ / 64, NHEAD), 256>>>(
                qkv + (long)b * TSEQ * C3, C3, HSZ,                    // Q base, head stride 64
                qkv + (long)b * TSEQ * C3 + CDIM, C3, HSZ,             // K base (transB)
                nullptr, nullptr,
                att + (long)b * NHEAD * TSEQ * TSEQ, TSEQ, (long)TSEQ * TSEQ,
                TSEQ, TSEQ, HSZ);
        }

        // fused scale + causal + key-mask + softmax
        softmax_mask_kernel<<<BBATCH * NHEAD * TSEQ, 256>>>(att, am);

        // importance = mean over heads & queries of att
        zero_kernel<<<NTOK / 256, 256>>>(imp, NTOK);
        imp_reduce_kernel<<<dim3(BBATCH, TSEQ / 256, 16), 256>>>(att, imp);

        // y = att @ V
        for (int b = 0; b < BBATCH; b++) {
            gemm_kernel<false, 0><<<dim3(1, TSEQ / 64, NHEAD), 256>>>(
                att + (long)b * NHEAD * TSEQ * TSEQ, TSEQ, (long)TSEQ * TSEQ,
                qkv + (long)b * TSEQ * C3 + 2 * CDIM, C3, HSZ,         // V
                nullptr, nullptr,
                y + (long)b * TSEQ * CDIM, CDIM, HSZ,
                TSEQ, HSZ, TSEQ);
        }

        // x = x + y @ proj_w + proj_b (residual fused)
        gemm_kernel<false, 0><<<dim3(CDIM / 64, NTOK / 64, 1), 256>>>(
            y, CDIM, 0,
            proj_w + (long)l * CDIM * CDIM, CDIM, 0,
            proj_b + (long)l * CDIM, x,
            x, CDIM, 0, NTOK, CDIM, CDIM);

        // prune: cm = am * pm; x *= cm (uses OLD am for this layer's attention already done)
        prune_mask_kernel<<<NTOK / 256, 256>>>(imp, am, thresholds, l);
        scale_rows_kernel<<<NTOK, 256>>>(x, am);

        // LN2
        ln_kernel<<<NTOK, 256>>>(x, ln2_w + (long)l * CDIM, ln2_b + (long)l * CDIM, h);

        // fc = gelu(h @ fc_w + fc_b)
        gemm_kernel<false, 1><<<dim3(C4 / 64, NTOK / 64, 1), 256>>>(
            h, CDIM, 0,
            fc_w + (long)l * CDIM * C4, C4, 0,
            fc_b + (long)l * C4, nullptr,
            fc, C4, 0, NTOK, C4, CDIM);

        // x = x + fc @ mlp_w + mlp_b
        gemm_kernel<false, 0><<<dim3(CDIM / 64, NTOK / 64, 1), 256>>>(
            fc, C4, 0,
            mlp_w + (long)l * C4 * CDIM, CDIM, 0,
            mlp_b + (long)l * CDIM, x,
            x, CDIM, 0, NTOK, CDIM, C4);
    }

    // final LN
    ln_kernel<<<NTOK, 256>>>(x, lnf_w, lnf_b, h);

    // logits = h @ wteᵀ  -> straight into d_out
    gemm_kernel<true, 0><<<dim3(VOCAB / 64, NTOK / 64, 1), 256>>>(
        h, CDIM, 0,
        wte, CDIM, 0,
        nullptr, nullptr,
        out, VOCAB, 0, NTOK, VOCAB, CDIM);

    // loss
    loss_row_kernel<<<NTOK, 256>>>(out, targets, nll);
    if ((long)out_size >= (long)NTOK * VOCAB + 1)
        loss_final_kernel<<<1, 256>>>(nll, targets, out + (long)NTOK * VOCAB);
}